// round 1
// baseline (speedup 1.0000x reference)
#include <cuda_runtime.h>

// out[t][l][d]: l==0 -> inputs[t][d], else memory[l][d]
// T=2048, L=64, D=1024 (fp32). Pure store-bandwidth kernel.
// One thread per float4 of output: 2048*64*256 = 33,554,432 threads.

static constexpr int T = 2048;
static constexpr int L = 64;
static constexpr int D = 1024;
static constexpr int D4 = D / 4;            // 256
static constexpr long TOTAL4 = (long)T * L * D4;

__global__ __launch_bounds__(256, 8)
void sliding_window_memory_kernel(const float4* __restrict__ in,
                                  const float4* __restrict__ mem,
                                  float4* __restrict__ out)
{
    long idx = (long)blockIdx.x * blockDim.x + threadIdx.x;
    if (idx >= TOTAL4) return;

    int d4 = (int)(idx & (D4 - 1));          // bits [0:8)
    int l  = (int)((idx >> 8) & (L - 1));    // bits [8:14)
    int t  = (int)(idx >> 14);               // bits [14:..)

    // l==0: inputs[t][d] ; else: memory[l][d] (tiny, L2-resident)
    const float4* __restrict__ src = (l == 0) ? (in + (long)t * D4 + d4)
                                              : (mem + (long)l * D4 + d4);
    out[idx] = *src;
}

extern "C" void kernel_launch(void* const* d_in, const int* in_sizes, int n_in,
                              void* d_out, int out_size)
{
    const float4* in  = (const float4*)d_in[0];   // inputs [T, D] fp32
    const float4* mem = (const float4*)d_in[1];   // memory [L, D] fp32
    float4* out = (float4*)d_out;                 // [T, L, D] fp32

    const int threads = 256;
    const int blocks = (int)((TOTAL4 + threads - 1) / threads);  // 131072
    sliding_window_memory_kernel<<<blocks, threads>>>(in, mem, out);
}

// round 2
// speedup vs baseline: 1.0921x; 1.0921x over previous
#include <cuda_runtime.h>

// out[t][l][d]: l==0 -> inputs[t][d], else memory[l][d]
// T=2048, L=64, D=1024 fp32. Pure store-bandwidth kernel (512 MiB writes).
//
// Layout: row = t*L + l, each row = D4=256 float4. A 256-thread block covers
// one row per unrolled step; each block handles U=8 consecutive rows.
// 8 independent LDG/STG pairs per thread -> MLP, amortized index math.

static constexpr int T = 2048;
static constexpr int L = 64;
static constexpr int D4 = 1024 / 4;            // 256 float4 per row
static constexpr int ROWS = T * L;             // 131072
static constexpr int U = 8;                    // rows per block

__global__ __launch_bounds__(256, 8)
void sliding_window_memory_kernel(const float4* __restrict__ in,
                                  const float4* __restrict__ mem,
                                  float4* __restrict__ out)
{
    const int tid = threadIdx.x;
    const int row0 = blockIdx.x * U;

    float4* __restrict__ o = out + (long)row0 * D4 + tid;

    float4 v[U];
#pragma unroll
    for (int u = 0; u < U; ++u) {
        const int row = row0 + u;
        const int l = row & (L - 1);
        const int t = row >> 6;
        const float4* __restrict__ s =
            (l == 0) ? (in + t * D4 + tid) : (mem + l * D4 + tid);
        v[u] = __ldg(s);                  // in: DRAM once; mem tail: L2-resident
    }
#pragma unroll
    for (int u = 0; u < U; ++u) {
        __stcs(o + u * D4, v[u]);         // streaming store: don't pollute L2
    }
}

extern "C" void kernel_launch(void* const* d_in, const int* in_sizes, int n_in,
                              void* d_out, int out_size)
{
    const float4* in  = (const float4*)d_in[0];   // inputs [T, D] fp32
    const float4* mem = (const float4*)d_in[1];   // memory [L, D] fp32
    float4* out = (float4*)d_out;                 // [T, L, D] fp32

    const int threads = 256;
    const int blocks = ROWS / U;                  // 16384
    sliding_window_memory_kernel<<<blocks, threads>>>(in, mem, out);
}